// round 1
// baseline (speedup 1.0000x reference)
#include <cuda_runtime.h>
#include <mma.h>
using namespace nvcuda;

// Problem dims (fixed by the reference)
#define HD   2048      // hidden
#define ID   16384     // intermediate
#define TT   8192      // tokens = B*S
#define NE   5         // num experts (router)
#define ELO  4         // lora experts
#define RNK  16        // lora rank

// Scratch (device globals: allocation-free per harness rules)
__device__ float g_h[(size_t)TT * ID];   // fused gelu(g)*u intermediate, 512MB
__device__ int   g_sel[TT];
__device__ float g_probs[NE];
__device__ float g_counts[NE];

__device__ __forceinline__ float gelu_tanh(float v) {
    const float c = 0.7978845608028654f;   // sqrt(2/pi)
    float t = c * (v + 0.044715f * v * v * v);
    return 0.5f * v * (1.0f + tanhf(t));
}

// ---------------------------------------------------------------------------
// 0) zero accumulators
__global__ void k_zero() {
    int i = threadIdx.x;
    if (i < NE) { g_probs[i] = 0.0f; g_counts[i] = 0.0f; }
}

// ---------------------------------------------------------------------------
// 1) router: logits, argmax sel, softmax stats. One warp per token.
__global__ void k_router(const float* __restrict__ x, const float* __restrict__ rw) {
    __shared__ float sp[NE];
    __shared__ float sc[NE];
    int tid = threadIdx.x, warp = tid >> 5, lane = tid & 31;
    if (tid < NE) { sp[tid] = 0.0f; sc[tid] = 0.0f; }
    __syncthreads();

    int t = blockIdx.x * 8 + warp;
    float acc[NE];
#pragma unroll
    for (int e = 0; e < NE; e++) acc[e] = 0.0f;
    const float* xr = x + (size_t)t * HD;
    for (int h = lane; h < HD; h += 32) {
        float xv = xr[h];
#pragma unroll
        for (int e = 0; e < NE; e++) acc[e] += xv * rw[e * HD + h];
    }
#pragma unroll
    for (int e = 0; e < NE; e++) {
#pragma unroll
        for (int off = 16; off > 0; off >>= 1)
            acc[e] += __shfl_down_sync(0xffffffffu, acc[e], off);
    }
    if (lane == 0) {
        int sel = 0; float m = acc[0];
#pragma unroll
        for (int e = 1; e < NE; e++) if (acc[e] > m) { m = acc[e]; sel = e; }
        float s = 0.0f, p[NE];
#pragma unroll
        for (int e = 0; e < NE; e++) { p[e] = __expf(acc[e] - m); s += p[e]; }
        float inv = 1.0f / s;
#pragma unroll
        for (int e = 0; e < NE; e++) atomicAdd(&sp[e], p[e] * inv);
        atomicAdd(&sc[sel], 1.0f);
        g_sel[t] = sel;
    }
    __syncthreads();
    if (tid < NE) {
        atomicAdd(&g_probs[tid], sp[tid]);
        atomicAdd(&g_counts[tid], sc[tid]);
    }
}

// ---------------------------------------------------------------------------
// 2) aux loss scalar -> d_out[TT*HD]
__global__ void k_aux(float* __restrict__ out) {
    float a = 0.0f;
    const float invT = 1.0f / (float)TT;
#pragma unroll
    for (int e = 0; e < NE; e++)
        a += (g_probs[e] * invT) * (g_counts[e] * invT);
    out[(size_t)TT * HD] = a * (float)NE * 0.01f;
}

// ---------------------------------------------------------------------------
// 3) fused gate/up GEMM: h[t,i] = gelu(x·gate_i) * (x·up_i)
//    C = A(x, row-major [TT,HD]) * B^T (gate/up row-major [ID,HD] == col-major KxN)
//    Tile: BM=128, BN=64, BK=32; 8 warps in 4x2; warp tile 32x32; tf32 m16n16k8
__global__ __launch_bounds__(256)
void k_gemm1(const float* __restrict__ x,
             const float* __restrict__ gw,
             const float* __restrict__ uw) {
    __shared__ float As[128][36];
    __shared__ float Bg[64][36];
    __shared__ float Bu[64][36];

    const int tid  = threadIdx.x;
    const int warp = tid >> 5;
    const int wm   = warp >> 1;   // 0..3
    const int wn   = warp & 1;    // 0..1
    const int row0 = blockIdx.y * 128;
    const int col0 = blockIdx.x * 64;

    wmma::fragment<wmma::accumulator, 16, 16, 8, float> cg[2][2], cu[2][2];
#pragma unroll
    for (int i = 0; i < 2; i++)
#pragma unroll
        for (int j = 0; j < 2; j++) {
            wmma::fill_fragment(cg[i][j], 0.0f);
            wmma::fill_fragment(cu[i][j], 0.0f);
        }

    const int lrow = tid >> 3;          // 0..31
    const int lcol = (tid & 7) * 4;     // 0..28

    for (int k0 = 0; k0 < HD; k0 += 32) {
        __syncthreads();
#pragma unroll
        for (int i = 0; i < 4; i++) {
            float4 v = *(const float4*)&x[(size_t)(row0 + lrow + i * 32) * HD + k0 + lcol];
            As[lrow + i * 32][lcol + 0] = wmma::__float_to_tf32(v.x);
            As[lrow + i * 32][lcol + 1] = wmma::__float_to_tf32(v.y);
            As[lrow + i * 32][lcol + 2] = wmma::__float_to_tf32(v.z);
            As[lrow + i * 32][lcol + 3] = wmma::__float_to_tf32(v.w);
        }
#pragma unroll
        for (int i = 0; i < 2; i++) {
            int r = lrow + i * 32;
            float4 v = *(const float4*)&gw[(size_t)(col0 + r) * HD + k0 + lcol];
            Bg[r][lcol + 0] = wmma::__float_to_tf32(v.x);
            Bg[r][lcol + 1] = wmma::__float_to_tf32(v.y);
            Bg[r][lcol + 2] = wmma::__float_to_tf32(v.z);
            Bg[r][lcol + 3] = wmma::__float_to_tf32(v.w);
            float4 u = *(const float4*)&uw[(size_t)(col0 + r) * HD + k0 + lcol];
            Bu[r][lcol + 0] = wmma::__float_to_tf32(u.x);
            Bu[r][lcol + 1] = wmma::__float_to_tf32(u.y);
            Bu[r][lcol + 2] = wmma::__float_to_tf32(u.z);
            Bu[r][lcol + 3] = wmma::__float_to_tf32(u.w);
        }
        __syncthreads();

#pragma unroll
        for (int kk = 0; kk < 32; kk += 8) {
            wmma::fragment<wmma::matrix_a, 16, 16, 8, wmma::precision::tf32, wmma::row_major> a[2];
            wmma::fragment<wmma::matrix_b, 16, 16, 8, wmma::precision::tf32, wmma::col_major> b[2];
#pragma unroll
            for (int i = 0; i < 2; i++)
                wmma::load_matrix_sync(a[i], &As[wm * 32 + 16 * i][kk], 36);
#pragma unroll
            for (int j = 0; j < 2; j++)
                wmma::load_matrix_sync(b[j], &Bg[wn * 32 + 16 * j][kk], 36);
#pragma unroll
            for (int i = 0; i < 2; i++)
#pragma unroll
                for (int j = 0; j < 2; j++)
                    wmma::mma_sync(cg[i][j], a[i], b[j], cg[i][j]);
#pragma unroll
            for (int j = 0; j < 2; j++)
                wmma::load_matrix_sync(b[j], &Bu[wn * 32 + 16 * j][kk], 36);
#pragma unroll
            for (int i = 0; i < 2; i++)
#pragma unroll
                for (int j = 0; j < 2; j++)
                    wmma::mma_sync(cu[i][j], a[i], b[j], cu[i][j]);
        }
    }

    // Epilogue: gelu(g)*u elementwise (identical fragment layouts), store to g_h
#pragma unroll
    for (int i = 0; i < 2; i++)
#pragma unroll
        for (int j = 0; j < 2; j++) {
#pragma unroll
            for (int e = 0; e < cg[i][j].num_elements; e++)
                cg[i][j].x[e] = gelu_tanh(cg[i][j].x[e]) * cu[i][j].x[e];
            float* dst = &g_h[(size_t)(row0 + wm * 32 + 16 * i) * ID + col0 + wn * 32 + 16 * j];
            wmma::store_matrix_sync(dst, cg[i][j], ID, wmma::mem_row_major);
        }
}

// ---------------------------------------------------------------------------
// 4) down GEMM: out[t,h] = h[t,:] · down_w[h,:]
//    Tile: BM=128, BN=128, BK=32; 8 warps 4x2; warp tile 32x64
__global__ __launch_bounds__(256)
void k_gemm2(const float* __restrict__ dw, float* __restrict__ out) {
    __shared__ float As[128][36];
    __shared__ float Bs[128][36];

    const int tid  = threadIdx.x;
    const int warp = tid >> 5;
    const int wm   = warp >> 1;   // 0..3
    const int wn   = warp & 1;    // 0..1
    const int row0 = blockIdx.y * 128;
    const int col0 = blockIdx.x * 128;

    wmma::fragment<wmma::accumulator, 16, 16, 8, float> c[2][4];
#pragma unroll
    for (int i = 0; i < 2; i++)
#pragma unroll
        for (int j = 0; j < 4; j++)
            wmma::fill_fragment(c[i][j], 0.0f);

    const int lrow = tid >> 3;
    const int lcol = (tid & 7) * 4;

    for (int k0 = 0; k0 < ID; k0 += 32) {
        __syncthreads();
#pragma unroll
        for (int i = 0; i < 4; i++) {
            int r = lrow + i * 32;
            float4 v = *(const float4*)&g_h[(size_t)(row0 + r) * ID + k0 + lcol];
            As[r][lcol + 0] = wmma::__float_to_tf32(v.x);
            As[r][lcol + 1] = wmma::__float_to_tf32(v.y);
            As[r][lcol + 2] = wmma::__float_to_tf32(v.z);
            As[r][lcol + 3] = wmma::__float_to_tf32(v.w);
            float4 b = *(const float4*)&dw[(size_t)(col0 + r) * ID + k0 + lcol];
            Bs[r][lcol + 0] = wmma::__float_to_tf32(b.x);
            Bs[r][lcol + 1] = wmma::__float_to_tf32(b.y);
            Bs[r][lcol + 2] = wmma::__float_to_tf32(b.z);
            Bs[r][lcol + 3] = wmma::__float_to_tf32(b.w);
        }
        __syncthreads();

#pragma unroll
        for (int kk = 0; kk < 32; kk += 8) {
            wmma::fragment<wmma::matrix_a, 16, 16, 8, wmma::precision::tf32, wmma::row_major> a[2];
            wmma::fragment<wmma::matrix_b, 16, 16, 8, wmma::precision::tf32, wmma::col_major> b[4];
#pragma unroll
            for (int i = 0; i < 2; i++)
                wmma::load_matrix_sync(a[i], &As[wm * 32 + 16 * i][kk], 36);
#pragma unroll
            for (int j = 0; j < 4; j++)
                wmma::load_matrix_sync(b[j], &Bs[wn * 64 + 16 * j][kk], 36);
#pragma unroll
            for (int i = 0; i < 2; i++)
#pragma unroll
                for (int j = 0; j < 4; j++)
                    wmma::mma_sync(c[i][j], a[i], b[j], c[i][j]);
        }
    }

#pragma unroll
    for (int i = 0; i < 2; i++)
#pragma unroll
        for (int j = 0; j < 4; j++) {
            float* dst = &out[(size_t)(row0 + wm * 32 + 16 * i) * HD + col0 + wn * 64 + 16 * j];
            wmma::store_matrix_sync(dst, c[i][j], HD, wmma::mem_row_major);
        }
}

// ---------------------------------------------------------------------------
// 5) LoRA correction: one CTA per token; skip tokens routed to expert 0.
__global__ __launch_bounds__(256)
void k_lora(const float* __restrict__ x,
            const float* __restrict__ la,   // [ELO, RNK, HD]
            const float* __restrict__ lb,   // [ELO, HD, RNK]
            float* __restrict__ out) {
    const int t = blockIdx.x;
    const int sel = g_sel[t];
    if (sel == 0) return;
    const int e = sel - 1;

    __shared__ float st[RNK];
    const int tid = threadIdx.x, warp = tid >> 5, lane = tid & 31;

    const float* Ae = la + (size_t)e * RNK * HD;
    const float* xr = x + (size_t)t * HD;
    float a0 = 0.0f, a1 = 0.0f;
    for (int h = lane; h < HD; h += 32) {
        float xv = xr[h];
        a0 += xv * Ae[warp * HD + h];
        a1 += xv * Ae[(warp + 8) * HD + h];
    }
#pragma unroll
    for (int off = 16; off > 0; off >>= 1) {
        a0 += __shfl_down_sync(0xffffffffu, a0, off);
        a1 += __shfl_down_sync(0xffffffffu, a1, off);
    }
    if (lane == 0) { st[warp] = a0; st[warp + 8] = a1; }
    __syncthreads();

    const float* Be = lb + (size_t)e * HD * RNK;
    float* orow = out + (size_t)t * HD;
    for (int h = tid; h < HD; h += 256) {
        float acc = 0.0f;
        const float4* b4 = (const float4*)&Be[h * RNK];
#pragma unroll
        for (int q = 0; q < 4; q++) {
            float4 bv = b4[q];
            acc += st[q * 4 + 0] * bv.x + st[q * 4 + 1] * bv.y +
                   st[q * 4 + 2] * bv.z + st[q * 4 + 3] * bv.w;
        }
        orow[h] += 2.0f * acc;   // LORA_SCALE
    }
}

// ---------------------------------------------------------------------------
extern "C" void kernel_launch(void* const* d_in, const int* in_sizes, int n_in,
                              void* d_out, int out_size) {
    const float* x  = (const float*)d_in[0];  // [4,2048,2048]
    const float* rw = (const float*)d_in[1];  // [5,2048]
    const float* gw = (const float*)d_in[2];  // [16384,2048]
    const float* uw = (const float*)d_in[3];  // [16384,2048]
    const float* dw = (const float*)d_in[4];  // [2048,16384]
    const float* la = (const float*)d_in[5];  // [4,16,2048]
    const float* lb = (const float*)d_in[6];  // [4,2048,16]
    float* out = (float*)d_out;               // [4,2048,2048] + aux scalar

    k_zero<<<1, 32>>>();
    k_router<<<TT / 8, 256>>>(x, rw);
    k_aux<<<1, 1>>>(out);

    dim3 g1(ID / 64, TT / 128);
    k_gemm1<<<g1, 256>>>(x, gw, uw);

    dim3 g2(HD / 128, TT / 128);
    k_gemm2<<<g2, 256>>>(dw, out);

    k_lora<<<TT, 256>>>(x, la, lb, out);
}

// round 3
// speedup vs baseline: 1.2269x; 1.2269x over previous
#include <cuda_runtime.h>
#include <cstdint>
#include <mma.h>
using namespace nvcuda;

// Problem dims (fixed by the reference)
#define HD   2048      // hidden
#define ID   16384     // intermediate
#define TT   8192      // tokens = B*S
#define NE   5         // num experts (router)
#define RNK  16        // lora rank

// Scratch (device globals: allocation-free per harness rules)
__device__ float g_h[(size_t)TT * ID];    // gelu(g)*u intermediate (tf32-rounded), 512MB
__device__ float g_x[(size_t)TT * HD];    // tf32-rounded x, 64MB
__device__ float g_gw[(size_t)ID * HD];   // tf32-rounded gate_w, 128MB
__device__ float g_uw[(size_t)ID * HD];   // tf32-rounded up_w, 128MB
__device__ float g_dw[(size_t)HD * ID];   // tf32-rounded down_w, 128MB
__device__ int   g_sel[TT];
__device__ float g_probs[NE];
__device__ float g_counts[NE];

// ---------------------------------------------------------------------------
// helpers
__device__ __forceinline__ float fast_tanh(float x) {
    float y;
    asm("tanh.approx.f32 %0, %1;" : "=f"(y) : "f"(x));
    return y;
}
__device__ __forceinline__ float gelu_tanh(float v) {
    const float c = 0.7978845608028654f;   // sqrt(2/pi)
    float t = c * (v + 0.044715f * v * v * v);
    return 0.5f * v * (1.0f + fast_tanh(t));
}
__device__ __forceinline__ void cp16(float* s, const float* g) {
    unsigned int sa = (unsigned int)__cvta_generic_to_shared(s);
    asm volatile("cp.async.cg.shared.global [%0], [%1], 16;" :: "r"(sa), "l"(g));
}
__device__ __forceinline__ void cp_commit() {
    asm volatile("cp.async.commit_group;");
}
template <int N>
__device__ __forceinline__ void cp_wait() {
    asm volatile("cp.async.wait_group %0;" :: "n"(N));
}

// ---------------------------------------------------------------------------
// 0) zero accumulators
__global__ void k_zero() {
    int i = threadIdx.x;
    if (i < NE) { g_probs[i] = 0.0f; g_counts[i] = 0.0f; }
}

// ---------------------------------------------------------------------------
// tf32 pre-conversion pass (round-to-nearest on 13 low mantissa bits)
__global__ void k_cvt(const float4* __restrict__ src, float4* __restrict__ dst, int n4) {
    int i = blockIdx.x * blockDim.x + threadIdx.x;
    if (i < n4) {
        float4 v = src[i];
        v.x = wmma::__float_to_tf32(v.x);
        v.y = wmma::__float_to_tf32(v.y);
        v.z = wmma::__float_to_tf32(v.z);
        v.w = wmma::__float_to_tf32(v.w);
        dst[i] = v;
    }
}

// ---------------------------------------------------------------------------
// 1) router: logits, argmax sel, softmax stats. One warp per token. (fp32 x)
__global__ void k_router(const float* __restrict__ x, const float* __restrict__ rw) {
    __shared__ float sp[NE];
    __shared__ float sc[NE];
    int tid = threadIdx.x, warp = tid >> 5, lane = tid & 31;
    if (tid < NE) { sp[tid] = 0.0f; sc[tid] = 0.0f; }
    __syncthreads();

    int t = blockIdx.x * 8 + warp;
    float acc[NE];
#pragma unroll
    for (int e = 0; e < NE; e++) acc[e] = 0.0f;
    const float* xr = x + (size_t)t * HD;
    for (int h = lane; h < HD; h += 32) {
        float xv = xr[h];
#pragma unroll
        for (int e = 0; e < NE; e++) acc[e] += xv * rw[e * HD + h];
    }
#pragma unroll
    for (int e = 0; e < NE; e++) {
#pragma unroll
        for (int off = 16; off > 0; off >>= 1)
            acc[e] += __shfl_down_sync(0xffffffffu, acc[e], off);
    }
    if (lane == 0) {
        int sel = 0; float m = acc[0];
#pragma unroll
        for (int e = 1; e < NE; e++) if (acc[e] > m) { m = acc[e]; sel = e; }
        float s = 0.0f, p[NE];
#pragma unroll
        for (int e = 0; e < NE; e++) { p[e] = __expf(acc[e] - m); s += p[e]; }
        float inv = 1.0f / s;
#pragma unroll
        for (int e = 0; e < NE; e++) atomicAdd(&sp[e], p[e] * inv);
        atomicAdd(&sc[sel], 1.0f);
        g_sel[t] = sel;
    }
    __syncthreads();
    if (tid < NE) {
        atomicAdd(&g_probs[tid], sp[tid]);
        atomicAdd(&g_counts[tid], sc[tid]);
    }
}

// ---------------------------------------------------------------------------
// 2) aux loss scalar -> d_out[TT*HD]
__global__ void k_aux(float* __restrict__ out) {
    float a = 0.0f;
    const float invT = 1.0f / (float)TT;
#pragma unroll
    for (int e = 0; e < NE; e++)
        a += (g_probs[e] * invT) * (g_counts[e] * invT);
    out[(size_t)TT * HD] = a * (float)NE * 0.01f;
}

// ---------------------------------------------------------------------------
// 3) fused gate/up GEMM: h[t,i] = gelu(x*gate_i) * (x*up_i)
//    3-stage cp.async pipeline. BM=128, BN=64, BK=32. 8 warps 4x2, warp 32x32.
//    Operands pre-rounded to tf32 -> no cvt in the mainloop.
#define G1_AS (128 * 36)
#define G1_BS (64 * 36)
__global__ __launch_bounds__(256, 2)
void k_gemm1(const float* __restrict__ X,
             const float* __restrict__ GW,
             const float* __restrict__ UW) {
    extern __shared__ float sm[];
    float* sA  = sm;                    // [3][128*36]
    float* sBg = sm + 3 * G1_AS;        // [3][64*36]
    float* sBu = sBg + 3 * G1_BS;       // [3][64*36]

    const int tid  = threadIdx.x;
    const int warp = tid >> 5;
    const int wm   = warp >> 1;        // 0..3
    const int wn   = warp & 1;         // 0..1
    const int row0 = blockIdx.x * 128; // token tile
    const int col0 = blockIdx.y * 64;  // intermediate tile
    const int lrow = tid >> 3;         // 0..31
    const int lcol = (tid & 7) * 4;    // 0..28

    wmma::fragment<wmma::accumulator, 16, 16, 8, float> cg[2][2], cu[2][2];
#pragma unroll
    for (int i = 0; i < 2; i++)
#pragma unroll
        for (int j = 0; j < 2; j++) {
            wmma::fill_fragment(cg[i][j], 0.0f);
            wmma::fill_fragment(cu[i][j], 0.0f);
        }

    auto prefetch = [&](int k0, int s) {
        float* a  = sA  + s * G1_AS;
        float* bg = sBg + s * G1_BS;
        float* bu = sBu + s * G1_BS;
#pragma unroll
        for (int i = 0; i < 4; i++)
            cp16(a + (lrow + i * 32) * 36 + lcol,
                 X + (size_t)(row0 + lrow + i * 32) * HD + k0 + lcol);
#pragma unroll
        for (int i = 0; i < 2; i++) {
            cp16(bg + (lrow + i * 32) * 36 + lcol,
                 GW + (size_t)(col0 + lrow + i * 32) * HD + k0 + lcol);
            cp16(bu + (lrow + i * 32) * 36 + lcol,
                 UW + (size_t)(col0 + lrow + i * 32) * HD + k0 + lcol);
        }
        cp_commit();
    };

    const int NITER = HD / 32;         // 64
    prefetch(0, 0);
    prefetch(32, 1);

    for (int it = 0; it < NITER; it++) {
        const int s = it % 3;
        cp_wait<1>();                   // stage `it` landed
        __syncthreads();

        const float* a  = sA  + s * G1_AS;
        const float* bg = sBg + s * G1_BS;
        const float* bu = sBu + s * G1_BS;
#pragma unroll
        for (int kk = 0; kk < 32; kk += 8) {
            wmma::fragment<wmma::matrix_a, 16, 16, 8, wmma::precision::tf32, wmma::row_major> af[2];
            wmma::fragment<wmma::matrix_b, 16, 16, 8, wmma::precision::tf32, wmma::col_major> bf[2];
#pragma unroll
            for (int i = 0; i < 2; i++)
                wmma::load_matrix_sync(af[i], a + (wm * 32 + 16 * i) * 36 + kk, 36);
#pragma unroll
            for (int j = 0; j < 2; j++)
                wmma::load_matrix_sync(bf[j], bg + (wn * 32 + 16 * j) * 36 + kk, 36);
#pragma unroll
            for (int i = 0; i < 2; i++)
#pragma unroll
                for (int j = 0; j < 2; j++)
                    wmma::mma_sync(cg[i][j], af[i], bf[j], cg[i][j]);
#pragma unroll
            for (int j = 0; j < 2; j++)
                wmma::load_matrix_sync(bf[j], bu + (wn * 32 + 16 * j) * 36 + kk, 36);
#pragma unroll
            for (int i = 0; i < 2; i++)
#pragma unroll
                for (int j = 0; j < 2; j++)
                    wmma::mma_sync(cu[i][j], af[i], bf[j], cu[i][j]);
        }

        if (it + 2 < NITER) prefetch((it + 2) * 32, (it + 2) % 3);
        else cp_commit();               // keep group count uniform
    }

    // Epilogue: gelu(g)*u, rounded to tf32 so gemm2 needs no cvt.
#pragma unroll
    for (int i = 0; i < 2; i++)
#pragma unroll
        for (int j = 0; j < 2; j++) {
#pragma unroll
            for (int e = 0; e < cg[i][j].num_elements; e++)
                cg[i][j].x[e] = wmma::__float_to_tf32(gelu_tanh(cg[i][j].x[e]) * cu[i][j].x[e]);
            float* dst = &g_h[(size_t)(row0 + wm * 32 + 16 * i) * ID + col0 + wn * 32 + 16 * j];
            wmma::store_matrix_sync(dst, cg[i][j], ID, wmma::mem_row_major);
        }
}

// ---------------------------------------------------------------------------
// 4) down GEMM: out[t,h] = h[t,:] . down_w[h,:]
//    3-stage cp.async. BM=128, BN=128, BK=32. 8 warps 4x2, warp 32x64.
#define G2_AS (128 * 36)
__global__ __launch_bounds__(256, 2)
void k_gemm2(const float* __restrict__ H,
             const float* __restrict__ DW,
             float* __restrict__ out) {
    extern __shared__ float sm[];
    float* sA = sm;                     // [3][128*36]
    float* sB = sm + 3 * G2_AS;         // [3][128*36]

    const int tid  = threadIdx.x;
    const int warp = tid >> 5;
    const int wm   = warp >> 1;
    const int wn   = warp & 1;
    const int col0 = blockIdx.x * 128;  // hidden tile
    const int row0 = blockIdx.y * 128;  // token tile
    const int lrow = tid >> 3;
    const int lcol = (tid & 7) * 4;

    wmma::fragment<wmma::accumulator, 16, 16, 8, float> c[2][4];
#pragma unroll
    for (int i = 0; i < 2; i++)
#pragma unroll
        for (int j = 0; j < 4; j++)
            wmma::fill_fragment(c[i][j], 0.0f);

    auto prefetch = [&](int k0, int s) {
        float* a = sA + s * G2_AS;
        float* b = sB + s * G2_AS;
#pragma unroll
        for (int i = 0; i < 4; i++) {
            int r = lrow + i * 32;
            cp16(a + r * 36 + lcol, H  + (size_t)(row0 + r) * ID + k0 + lcol);
            cp16(b + r * 36 + lcol, DW + (size_t)(col0 + r) * ID + k0 + lcol);
        }
        cp_commit();
    };

    const int NITER = ID / 32;          // 512
    prefetch(0, 0);
    prefetch(32, 1);

    for (int it = 0; it < NITER; it++) {
        const int s = it % 3;
        cp_wait<1>();
        __syncthreads();

        const float* a = sA + s * G2_AS;
        const float* b = sB + s * G2_AS;
#pragma unroll
        for (int kk = 0; kk < 32; kk += 8) {
            wmma::fragment<wmma::matrix_a, 16, 16, 8, wmma::precision::tf32, wmma::row_major> af[2];
            wmma::fragment<wmma::matrix_b, 16, 16, 8, wmma::precision::tf32, wmma::col_major> bf[4];
#pragma unroll
            for (int i = 0; i < 2; i++)
                wmma::load_matrix_sync(af[i], a + (wm * 32 + 16 * i) * 36 + kk, 36);
#pragma unroll
            for (int j = 0; j < 4; j++)
                wmma::load_matrix_sync(bf[j], b + (wn * 64 + 16 * j) * 36 + kk, 36);
#pragma unroll
            for (int i = 0; i < 2; i++)
#pragma unroll
                for (int j = 0; j < 4; j++)
                    wmma::mma_sync(c[i][j], af[i], bf[j], c[i][j]);
        }

        if (it + 2 < NITER) prefetch((it + 2) * 32, (it + 2) % 3);
        else cp_commit();
    }

#pragma unroll
    for (int i = 0; i < 2; i++)
#pragma unroll
        for (int j = 0; j < 4; j++) {
            float* dst = &out[(size_t)(row0 + wm * 32 + 16 * i) * HD + col0 + wn * 64 + 16 * j];
            wmma::store_matrix_sync(dst, c[i][j], HD, wmma::mem_row_major);
        }
}

// ---------------------------------------------------------------------------
// 5) LoRA correction: one CTA per token; skip tokens routed to expert 0.
__global__ __launch_bounds__(256)
void k_lora(const float* __restrict__ x,
            const float* __restrict__ la,   // [4, RNK, HD]
            const float* __restrict__ lb,   // [4, HD, RNK]
            float* __restrict__ out) {
    const int t = blockIdx.x;
    const int sel = g_sel[t];
    if (sel == 0) return;
    const int e = sel - 1;

    __shared__ float st[RNK];
    const int tid = threadIdx.x, warp = tid >> 5, lane = tid & 31;

    const float* Ae = la + (size_t)e * RNK * HD;
    const float* xr = x + (size_t)t * HD;
    float a0 = 0.0f, a1 = 0.0f;
    for (int h = lane; h < HD; h += 32) {
        float xv = xr[h];
        a0 += xv * Ae[warp * HD + h];
        a1 += xv * Ae[(warp + 8) * HD + h];
    }
#pragma unroll
    for (int off = 16; off > 0; off >>= 1) {
        a0 += __shfl_down_sync(0xffffffffu, a0, off);
        a1 += __shfl_down_sync(0xffffffffu, a1, off);
    }
    if (lane == 0) { st[warp] = a0; st[warp + 8] = a1; }
    __syncthreads();

    const float* Be = lb + (size_t)e * HD * RNK;
    float* orow = out + (size_t)t * HD;
    for (int h = tid; h < HD; h += 256) {
        float acc = 0.0f;
        const float4* b4 = (const float4*)&Be[h * RNK];
#pragma unroll
        for (int q = 0; q < 4; q++) {
            float4 bv = b4[q];
            acc += st[q * 4 + 0] * bv.x + st[q * 4 + 1] * bv.y +
                   st[q * 4 + 2] * bv.z + st[q * 4 + 3] * bv.w;
        }
        orow[h] += 2.0f * acc;   // LORA_SCALE
    }
}

// ---------------------------------------------------------------------------
extern "C" void kernel_launch(void* const* d_in, const int* in_sizes, int n_in,
                              void* d_out, int out_size) {
    const float* x  = (const float*)d_in[0];  // [4,2048,2048]
    const float* rw = (const float*)d_in[1];  // [5,2048]
    const float* gw = (const float*)d_in[2];  // [16384,2048]
    const float* uw = (const float*)d_in[3];  // [16384,2048]
    const float* dw = (const float*)d_in[4];  // [2048,16384]
    const float* la = (const float*)d_in[5];  // [4,16,2048]
    const float* lb = (const float*)d_in[6];  // [4,2048,16]
    float* out = (float*)d_out;               // [4,2048,2048] + aux scalar

    const int SMEM1 = 3 * (G1_AS + 2 * G1_BS) * 4;   // 110592 B
    const int SMEM2 = 3 * (2 * G2_AS) * 4;           // 110592 B
    cudaFuncSetAttribute(k_gemm1, cudaFuncAttributeMaxDynamicSharedMemorySize, SMEM1);
    cudaFuncSetAttribute(k_gemm2, cudaFuncAttributeMaxDynamicSharedMemorySize, SMEM2);

    // scratch pointers for conversion targets
    float* p_x;  cudaGetSymbolAddress((void**)&p_x,  g_x);
    float* p_gw; cudaGetSymbolAddress((void**)&p_gw, g_gw);
    float* p_uw; cudaGetSymbolAddress((void**)&p_uw, g_uw);
    float* p_dw; cudaGetSymbolAddress((void**)&p_dw, g_dw);
    float* p_h;  cudaGetSymbolAddress((void**)&p_h,  g_h);

    k_zero<<<1, 32>>>();
    k_router<<<TT / 8, 256>>>(x, rw);
    k_aux<<<1, 1>>>(out);

    // tf32 pre-conversion (float4-vectorized)
    {
        int n4x = TT * HD / 4;            // 4,194,304
        int n4w = ID * HD / 4;            // 8,388,608
        k_cvt<<<n4x / 256, 256>>>((const float4*)x,  (float4*)p_x,  n4x);
        k_cvt<<<n4w / 256, 256>>>((const float4*)gw, (float4*)p_gw, n4w);
        k_cvt<<<n4w / 256, 256>>>((const float4*)uw, (float4*)p_uw, n4w);
        k_cvt<<<n4w / 256, 256>>>((const float4*)dw, (float4*)p_dw, n4w);
    }

    dim3 g1(TT / 128, ID / 64);           // x = token tile (L2 reuse of x)
    k_gemm1<<<g1, 256, SMEM1>>>(p_x, p_gw, p_uw);

    dim3 g2(HD / 128, TT / 128);          // x = hidden tile
    k_gemm2<<<g2, 256, SMEM2>>>(p_h, p_dw, out);

    k_lora<<<TT, 256>>>(x, la, lb, out);
}

// round 10
// speedup vs baseline: 5.5281x; 4.5057x over previous
#include <cuda_runtime.h>
#include <cuda_fp16.h>
#include <cstdint>
#include <mma.h>
using namespace nvcuda;

// Problem dims
#define HD   2048
#define ID   16384
#define TT   8192
#define NE   5
#define RNK  16

// Scratch (device globals)
__device__ __half g_h[(size_t)TT * ID];     // gelu(g)*u intermediate, fp16 (256MB)
__device__ __half g_xh[(size_t)TT * HD];    // fp16 x (32MB)
__device__ __half g_gwh[(size_t)ID * HD];   // fp16 gate_w (64MB)
__device__ __half g_uwh[(size_t)ID * HD];   // fp16 up_w (64MB)
__device__ __half g_dwh[(size_t)HD * ID];   // fp16 down_w (64MB)
__device__ int    g_sel[TT];
__device__ float  g_probs[NE];
__device__ float  g_counts[NE];

// ---------------------------------------------------------------------------
__device__ __forceinline__ uint32_t smem_u32(const void* p) {
    return (uint32_t)__cvta_generic_to_shared(p);
}
__device__ __forceinline__ void cp16s(uint32_t saddr, const void* g) {
    asm volatile("cp.async.cg.shared.global [%0], [%1], 16;" :: "r"(saddr), "l"(g));
}
__device__ __forceinline__ void cp_commit() { asm volatile("cp.async.commit_group;"); }
template <int N> __device__ __forceinline__ void cp_wait() {
    asm volatile("cp.async.wait_group %0;" :: "n"(N));
}
__device__ __forceinline__ float fast_tanh(float x) {
    float y; asm("tanh.approx.f32 %0, %1;" : "=f"(y) : "f"(x)); return y;
}
__device__ __forceinline__ float gelu_tanh(float v) {
    const float c = 0.7978845608028654f;
    float t = c * (v + 0.044715f * v * v * v);
    return 0.5f * v * (1.0f + fast_tanh(t));
}

// ---------------------------------------------------------------------------
__global__ void k_zero() {
    int i = threadIdx.x;
    if (i < NE) { g_probs[i] = 0.0f; g_counts[i] = 0.0f; }
}

// fp32 -> fp16 conversion (vectorized: 4 floats in, 4 halves out)
__global__ void k_cvt_h(const float4* __restrict__ src, uint2* __restrict__ dst, int n4) {
    int i = blockIdx.x * blockDim.x + threadIdx.x;
    if (i < n4) {
        float4 v = src[i];
        union { __half2 h[2]; uint2 u; } tmp;
        tmp.h[0] = __floats2half2_rn(v.x, v.y);
        tmp.h[1] = __floats2half2_rn(v.z, v.w);
        dst[i] = tmp.u;
    }
}

// router: one warp per token (fp32)
__global__ void k_router(const float* __restrict__ x, const float* __restrict__ rw) {
    __shared__ float sp[NE];
    __shared__ float sc[NE];
    int tid = threadIdx.x, warp = tid >> 5, lane = tid & 31;
    if (tid < NE) { sp[tid] = 0.0f; sc[tid] = 0.0f; }
    __syncthreads();

    int t = blockIdx.x * 8 + warp;
    float acc[NE];
#pragma unroll
    for (int e = 0; e < NE; e++) acc[e] = 0.0f;
    const float* xr = x + (size_t)t * HD;
    for (int h = lane; h < HD; h += 32) {
        float xv = xr[h];
#pragma unroll
        for (int e = 0; e < NE; e++) acc[e] += xv * rw[e * HD + h];
    }
#pragma unroll
    for (int e = 0; e < NE; e++) {
#pragma unroll
        for (int off = 16; off > 0; off >>= 1)
            acc[e] += __shfl_down_sync(0xffffffffu, acc[e], off);
    }
    if (lane == 0) {
        int sel = 0; float m = acc[0];
#pragma unroll
        for (int e = 1; e < NE; e++) if (acc[e] > m) { m = acc[e]; sel = e; }
        float s = 0.0f, p[NE];
#pragma unroll
        for (int e = 0; e < NE; e++) { p[e] = __expf(acc[e] - m); s += p[e]; }
        float inv = 1.0f / s;
#pragma unroll
        for (int e = 0; e < NE; e++) atomicAdd(&sp[e], p[e] * inv);
        atomicAdd(&sc[sel], 1.0f);
        g_sel[t] = sel;
    }
    __syncthreads();
    if (tid < NE) {
        atomicAdd(&g_probs[tid], sp[tid]);
        atomicAdd(&g_counts[tid], sc[tid]);
    }
}

__global__ void k_aux(float* __restrict__ out) {
    float a = 0.0f;
    const float invT = 1.0f / (float)TT;
#pragma unroll
    for (int e = 0; e < NE; e++)
        a += (g_probs[e] * invT) * (g_counts[e] * invT);
    out[(size_t)TT * HD] = a * (float)NE * 0.01f;
}

// ---------------------------------------------------------------------------
// gemm1 (fp16 wmma m16n16k16): h[t,i] = gelu(x*gate_i) * (x*up_i)
// BM=128, BN=64, BK=64; 3-stage cp.async; 8 warps 4x2, warp tile 32x32.
// Stage: A 128x72h (18432B) + Bg 64x72h (9216B) + Bu (9216B) = 36864B.
#define G1_STG 36864
#define LDH    72
__global__ __launch_bounds__(256, 2)
void k_gemm1(const __half* __restrict__ X,
             const __half* __restrict__ GW,
             const __half* __restrict__ UW,
             __half* __restrict__ Hout) {
    extern __shared__ __align__(16) char smem[];
    const int tid  = threadIdx.x;
    const int warp = tid >> 5;
    const int wm   = warp >> 1;        // 0..3
    const int wn   = warp & 1;         // 0..1
    const int row0 = blockIdx.x * 128; // token tile
    const int col0 = blockIdx.y * 64;  // intermediate tile

    wmma::fragment<wmma::accumulator, 16, 16, 16, float> cg[2][2], cu[2][2];
#pragma unroll
    for (int i = 0; i < 2; i++)
#pragma unroll
        for (int j = 0; j < 2; j++) {
            wmma::fill_fragment(cg[i][j], 0.0f);
            wmma::fill_fragment(cu[i][j], 0.0f);
        }

    auto prefetch = [&](int kt, int s) {
        const int k0 = kt * 64;
        __half* a  = (__half*)(smem + s * G1_STG);
        __half* bg = (__half*)(smem + s * G1_STG + 18432);
        __half* bu = (__half*)(smem + s * G1_STG + 27648);
#pragma unroll
        for (int i = 0; i < 4; i++) {
            int c = tid + i * 256;          // 0..1023
            int r = c >> 3, kc = c & 7;
            cp16s(smem_u32(a + r * LDH + kc * 8),
                  X + (size_t)(row0 + r) * HD + k0 + kc * 8);
        }
#pragma unroll
        for (int i = 0; i < 2; i++) {
            int c = tid + i * 256;          // 0..511
            int r = c >> 3, kc = c & 7;
            cp16s(smem_u32(bg + r * LDH + kc * 8),
                  GW + (size_t)(col0 + r) * HD + k0 + kc * 8);
            cp16s(smem_u32(bu + r * LDH + kc * 8),
                  UW + (size_t)(col0 + r) * HD + k0 + kc * 8);
        }
        cp_commit();
    };

    const int NITER = HD / 64;             // 32
    prefetch(0, 0);
    prefetch(1, 1);

    for (int it = 0; it < NITER; it++) {
        const int s = it % 3;
        cp_wait<1>();
        __syncthreads();

        const __half* a  = (const __half*)(smem + s * G1_STG);
        const __half* bg = (const __half*)(smem + s * G1_STG + 18432);
        const __half* bu = (const __half*)(smem + s * G1_STG + 27648);
#pragma unroll
        for (int kk = 0; kk < 64; kk += 16) {
            wmma::fragment<wmma::matrix_a, 16, 16, 16, __half, wmma::row_major> af[2];
            wmma::fragment<wmma::matrix_b, 16, 16, 16, __half, wmma::col_major> bf[2];
#pragma unroll
            for (int i = 0; i < 2; i++)
                wmma::load_matrix_sync(af[i], a + (wm * 32 + 16 * i) * LDH + kk, LDH);
#pragma unroll
            for (int j = 0; j < 2; j++)
                wmma::load_matrix_sync(bf[j], bg + (wn * 32 + 16 * j) * LDH + kk, LDH);
#pragma unroll
            for (int i = 0; i < 2; i++)
#pragma unroll
                for (int j = 0; j < 2; j++)
                    wmma::mma_sync(cg[i][j], af[i], bf[j], cg[i][j]);
#pragma unroll
            for (int j = 0; j < 2; j++)
                wmma::load_matrix_sync(bf[j], bu + (wn * 32 + 16 * j) * LDH + kk, LDH);
#pragma unroll
            for (int i = 0; i < 2; i++)
#pragma unroll
                for (int j = 0; j < 2; j++)
                    wmma::mma_sync(cu[i][j], af[i], bf[j], cu[i][j]);
        }

        if (it + 2 < NITER) prefetch(it + 2, (it + 2) % 3);
        else cp_commit();
    }

    // Epilogue: stage accumulators in smem, fuse gelu(g)*u, emit half2.
    __syncthreads();
    float* eg = (float*)smem;                 // 128x64 f32 = 32KB
    float* eu = (float*)(smem + 32768);       // 128x64 f32 = 32KB
#pragma unroll
    for (int i = 0; i < 2; i++)
#pragma unroll
        for (int j = 0; j < 2; j++) {
            wmma::store_matrix_sync(eg + (wm * 32 + 16 * i) * 64 + wn * 32 + 16 * j,
                                    cg[i][j], 64, wmma::mem_row_major);
            wmma::store_matrix_sync(eu + (wm * 32 + 16 * i) * 64 + wn * 32 + 16 * j,
                                    cu[i][j], 64, wmma::mem_row_major);
        }
    __syncthreads();
#pragma unroll
    for (int i = 0; i < 16; i++) {
        int idx = tid + i * 256;              // half2 unit, 0..4095
        int e = idx * 2;
        int m = e >> 6, n = e & 63;
        float g0 = eg[m * 64 + n],     u0 = eu[m * 64 + n];
        float g1 = eg[m * 64 + n + 1], u1 = eu[m * 64 + n + 1];
        __half2 h = __floats2half2_rn(gelu_tanh(g0) * u0, gelu_tanh(g1) * u1);
        *(__half2*)(Hout + (size_t)(row0 + m) * ID + col0 + n) = h;
    }
}

// ---------------------------------------------------------------------------
// gemm2 (fp16 wmma): out[t,h] = h[t,:] . down_w[h,:]
// BM=128, BN=128, BK=64; 3-stage; 8 warps 4x2, warp tile 32x64.
// Stage: A 128x72h + B 128x72h = 36864B.
#define G2_STG 36864
__global__ __launch_bounds__(256, 2)
void k_gemm2(const __half* __restrict__ Hin,
             const __half* __restrict__ DW,
             float* __restrict__ out) {
    extern __shared__ __align__(16) char smem[];
    const int tid  = threadIdx.x;
    const int warp = tid >> 5;
    const int wm   = warp >> 1;
    const int wn   = warp & 1;
    const int row0 = blockIdx.x * 128;  // token tile
    const int col0 = blockIdx.y * 128;  // hidden tile

    wmma::fragment<wmma::accumulator, 16, 16, 16, float> c[2][4];
#pragma unroll
    for (int i = 0; i < 2; i++)
#pragma unroll
        for (int j = 0; j < 4; j++)
            wmma::fill_fragment(c[i][j], 0.0f);

    auto prefetch = [&](int kt, int s) {
        const int k0 = kt * 64;
        __half* a = (__half*)(smem + s * G2_STG);
        __half* b = (__half*)(smem + s * G2_STG + 18432);
#pragma unroll
        for (int i = 0; i < 4; i++) {
            int cix = tid + i * 256;        // 0..1023
            int r = cix >> 3, kc = cix & 7;
            cp16s(smem_u32(a + r * LDH + kc * 8),
                  Hin + (size_t)(row0 + r) * ID + k0 + kc * 8);
            cp16s(smem_u32(b + r * LDH + kc * 8),
                  DW + (size_t)(col0 + r) * ID + k0 + kc * 8);
        }
        cp_commit();
    };

    const int NITER = ID / 64;              // 256
    prefetch(0, 0);
    prefetch(1, 1);

    for (int it = 0; it < NITER; it++) {
        const int s = it % 3;
        cp_wait<1>();
        __syncthreads();

        const __half* a = (const __half*)(smem + s * G2_STG);
        const __half* b = (const __half*)(smem + s * G2_STG + 18432);
#pragma unroll
        for (int kk = 0; kk < 64; kk += 16) {
            wmma::fragment<wmma::matrix_a, 16, 16, 16, __half, wmma::row_major> af[2];
            wmma::fragment<wmma::matrix_b, 16, 16, 16, __half, wmma::col_major> bf[4];
#pragma unroll
            for (int i = 0; i < 2; i++)
                wmma::load_matrix_sync(af[i], a + (wm * 32 + 16 * i) * LDH + kk, LDH);
#pragma unroll
            for (int j = 0; j < 4; j++)
                wmma::load_matrix_sync(bf[j], b + (wn * 64 + 16 * j) * LDH + kk, LDH);
#pragma unroll
            for (int i = 0; i < 2; i++)
#pragma unroll
                for (int j = 0; j < 4; j++)
                    wmma::mma_sync(c[i][j], af[i], bf[j], c[i][j]);
        }

        if (it + 2 < NITER) prefetch(it + 2, (it + 2) % 3);
        else cp_commit();
    }

#pragma unroll
    for (int i = 0; i < 2; i++)
#pragma unroll
        for (int j = 0; j < 4; j++) {
            float* dst = &out[(size_t)(row0 + wm * 32 + 16 * i) * HD + col0 + wn * 64 + 16 * j];
            wmma::store_matrix_sync(dst, c[i][j], HD, wmma::mem_row_major);
        }
}

// ---------------------------------------------------------------------------
// LoRA correction (fp32, unchanged)
__global__ __launch_bounds__(256)
void k_lora(const float* __restrict__ x,
            const float* __restrict__ la,
            const float* __restrict__ lb,
            float* __restrict__ out) {
    const int t = blockIdx.x;
    const int sel = g_sel[t];
    if (sel == 0) return;
    const int e = sel - 1;

    __shared__ float st[RNK];
    const int tid = threadIdx.x, warp = tid >> 5, lane = tid & 31;

    const float* Ae = la + (size_t)e * RNK * HD;
    const float* xr = x + (size_t)t * HD;
    float a0 = 0.0f, a1 = 0.0f;
    for (int h = lane; h < HD; h += 32) {
        float xv = xr[h];
        a0 += xv * Ae[warp * HD + h];
        a1 += xv * Ae[(warp + 8) * HD + h];
    }
#pragma unroll
    for (int off = 16; off > 0; off >>= 1) {
        a0 += __shfl_down_sync(0xffffffffu, a0, off);
        a1 += __shfl_down_sync(0xffffffffu, a1, off);
    }
    if (lane == 0) { st[warp] = a0; st[warp + 8] = a1; }
    __syncthreads();

    const float* Be = lb + (size_t)e * HD * RNK;
    float* orow = out + (size_t)t * HD;
    for (int h = tid; h < HD; h += 256) {
        float acc = 0.0f;
        const float4* b4 = (const float4*)&Be[h * RNK];
#pragma unroll
        for (int q = 0; q < 4; q++) {
            float4 bv = b4[q];
            acc += st[q * 4 + 0] * bv.x + st[q * 4 + 1] * bv.y +
                   st[q * 4 + 2] * bv.z + st[q * 4 + 3] * bv.w;
        }
        orow[h] += 2.0f * acc;
    }
}

// ---------------------------------------------------------------------------
extern "C" void kernel_launch(void* const* d_in, const int* in_sizes, int n_in,
                              void* d_out, int out_size) {
    const float* x  = (const float*)d_in[0];
    const float* rw = (const float*)d_in[1];
    const float* gw = (const float*)d_in[2];
    const float* uw = (const float*)d_in[3];
    const float* dw = (const float*)d_in[4];
    const float* la = (const float*)d_in[5];
    const float* lb = (const float*)d_in[6];
    float* out = (float*)d_out;

    const int SMEM1 = 3 * G1_STG;   // 110592 B
    const int SMEM2 = 3 * G2_STG;   // 110592 B
    cudaFuncSetAttribute(k_gemm1, cudaFuncAttributeMaxDynamicSharedMemorySize, SMEM1);
    cudaFuncSetAttribute(k_gemm2, cudaFuncAttributeMaxDynamicSharedMemorySize, SMEM2);

    __half* p_xh;  cudaGetSymbolAddress((void**)&p_xh,  g_xh);
    __half* p_gwh; cudaGetSymbolAddress((void**)&p_gwh, g_gwh);
    __half* p_uwh; cudaGetSymbolAddress((void**)&p_uwh, g_uwh);
    __half* p_dwh; cudaGetSymbolAddress((void**)&p_dwh, g_dwh);
    __half* p_h;   cudaGetSymbolAddress((void**)&p_h,   g_h);

    k_zero<<<1, 32>>>();
    k_router<<<TT / 8, 256>>>(x, rw);
    k_aux<<<1, 1>>>(out);

    {
        int n4x = TT * HD / 4;           // 4,194,304
        int n4w = ID * HD / 4;           // 8,388,608
        k_cvt_h<<<n4x / 256, 256>>>((const float4*)x,  (uint2*)p_xh,  n4x);
        k_cvt_h<<<n4w / 256, 256>>>((const float4*)gw, (uint2*)p_gwh, n4w);
        k_cvt_h<<<n4w / 256, 256>>>((const float4*)uw, (uint2*)p_uwh, n4w);
        k_cvt_h<<<n4w / 256, 256>>>((const float4*)dw, (uint2*)p_dwh, n4w);
    }

    dim3 g1(TT / 128, ID / 64);          // token tile fast: x resident in L2
    k_gemm1<<<g1, 256, SMEM1>>>(p_xh, p_gwh, p_uwh, p_h);

    dim3 g2(TT / 128, HD / 128);         // token tile fast: dw panel reused
    k_gemm2<<<g2, 256, SMEM2>>>(p_h, p_dwh, out);

    k_lora<<<TT, 256>>>(x, la, lb, out);
}